// round 2
// baseline (speedup 1.0000x reference)
#include <cuda_runtime.h>
#include <math.h>

// Problem constants
#define HID   1024
#define NB    256
#define L_SEQ 512
#define NH    (NB * HID)      // 262144
#define NBLK  128             // persistent blocks (<= 148 SMs -> co-resident)
#define NTHR  256

// ---------------------------------------------------------------------------
// Device-global scratch (no allocation anywhere)
// ---------------------------------------------------------------------------
__device__ float g_h0a[NH], g_h0b[NH];   // layer-0 h ping-pong
__device__ float g_h1a[NH], g_h1b[NH];   // layer-1 h ping-pong
__device__ float g_c0[NH],  g_c1[NH];    // cell states
__device__ unsigned g_count = 0;         // barrier arrival counter
__device__ unsigned g_gen   = 0;         // barrier generation

__device__ __forceinline__ float sigm(float x) { return 1.0f / (1.0f + __expf(-x)); }

// Software grid barrier: valid because all NBLK blocks are co-resident.
__device__ __forceinline__ void grid_sync()
{
    __syncthreads();
    if (threadIdx.x == 0) {
        __threadfence();
        unsigned g = *(volatile unsigned*)&g_gen;
        if (atomicAdd(&g_count, 1u) == NBLK - 1) {
            g_count = 0;
            __threadfence();
            atomicAdd(&g_gen, 1u);
        } else {
            while (*(volatile unsigned*)&g_gen == g) { }
        }
        __threadfence();
    }
    __syncthreads();
}

// ---------------------------------------------------------------------------
// 128(m) x 64(n) tile GEMM-accumulate over K=1024, NT form:
//   acc[i][g] += sum_k A[mb+m][k] * W[wrow(g,u)][k]
// Thread microtile: 8 m-rows x 4 gate-columns (same hidden unit u).
// Software-pipelined: next chunk's global loads issued before current compute.
// ---------------------------------------------------------------------------
__device__ __forceinline__ void gemm1024(
    const float* __restrict__ A,      // pre-offset to batch row mb (row-major, 1024)
    const float* __restrict__ Wr,     // pre-offset to this loader thread's W row
    float (&acc)[8][4],
    float (*As)[128], float (*Bs)[64],
    int lm, int lk4, int lc, int lkb, int m0, int u)
{
    const float* Ap = A + lm * HID + lk4;
    const float* Bp = Wr + lkb;

    float4 av0 = *(const float4*)(Ap);
    float4 av1 = *(const float4*)(Ap + 8);
    float4 bv  = *(const float4*)(Bp);

    #pragma unroll 1
    for (int k0 = 0; k0 < HID; k0 += 16) {
        __syncthreads();                       // previous tile fully consumed
        As[lk4 + 0][lm] = av0.x; As[lk4 + 1][lm] = av0.y;
        As[lk4 + 2][lm] = av0.z; As[lk4 + 3][lm] = av0.w;
        As[lk4 + 8][lm] = av1.x; As[lk4 + 9][lm] = av1.y;
        As[lk4 +10][lm] = av1.z; As[lk4 +11][lm] = av1.w;
        Bs[lkb + 0][lc] = bv.x;  Bs[lkb + 1][lc] = bv.y;
        Bs[lkb + 2][lc] = bv.z;  Bs[lkb + 3][lc] = bv.w;
        __syncthreads();

        if (k0 + 16 < HID) {                   // prefetch next chunk
            av0 = *(const float4*)(Ap + k0 + 16);
            av1 = *(const float4*)(Ap + k0 + 24);
            bv  = *(const float4*)(Bp + k0 + 16);
        }

        #pragma unroll
        for (int kk = 0; kk < 16; ++kk) {
            float4 a0 = *(const float4*)&As[kk][m0];
            float4 a1 = *(const float4*)&As[kk][m0 + 4];
            float b0 = Bs[kk][u];
            float b1 = Bs[kk][16 + u];
            float b2 = Bs[kk][32 + u];
            float b3 = Bs[kk][48 + u];
            acc[0][0] += a0.x * b0; acc[0][1] += a0.x * b1; acc[0][2] += a0.x * b2; acc[0][3] += a0.x * b3;
            acc[1][0] += a0.y * b0; acc[1][1] += a0.y * b1; acc[1][2] += a0.y * b2; acc[1][3] += a0.y * b3;
            acc[2][0] += a0.z * b0; acc[2][1] += a0.z * b1; acc[2][2] += a0.z * b2; acc[2][3] += a0.z * b3;
            acc[3][0] += a0.w * b0; acc[3][1] += a0.w * b1; acc[3][2] += a0.w * b2; acc[3][3] += a0.w * b3;
            acc[4][0] += a1.x * b0; acc[4][1] += a1.x * b1; acc[4][2] += a1.x * b2; acc[4][3] += a1.x * b3;
            acc[5][0] += a1.y * b0; acc[5][1] += a1.y * b1; acc[5][2] += a1.y * b2; acc[5][3] += a1.y * b3;
            acc[6][0] += a1.z * b0; acc[6][1] += a1.z * b1; acc[6][2] += a1.z * b2; acc[6][3] += a1.z * b3;
            acc[7][0] += a1.w * b0; acc[7][1] += a1.w * b1; acc[7][2] += a1.w * b2; acc[7][3] += a1.w * b3;
        }
    }
}

// ---------------------------------------------------------------------------
// One persistent kernel: zero-init, 512 x (layer0 step, layer1 step), linear.
// Block b owns batch rows [ (b&1)*128, +128 ) and hidden units [ (b>>1)*16, +16 )
// (x all 4 gates). Same ownership every step -> cell state is block-private.
// ---------------------------------------------------------------------------
__global__ void __launch_bounds__(NTHR, 1) lstm_persist(
    const float* __restrict__ seq,
    const float* __restrict__ Wih0, const float* __restrict__ Whh0,
    const float* __restrict__ bih0, const float* __restrict__ bhh0,
    const float* __restrict__ Wih1, const float* __restrict__ Whh1,
    const float* __restrict__ bih1, const float* __restrict__ bhh1,
    const float* __restrict__ linW, const float* __restrict__ linb,
    float* __restrict__ out)
{
    __shared__ float As[16][128];
    __shared__ float Bs[16][64];
    __shared__ float Xs[128][8];     // layer-0 x tile (6 used, padded)
    __shared__ float Ws6[64][8];     // layer-0 Wih tile (6 used, padded)
    __shared__ float red[8];

    const int tid = threadIdx.x;
    const int bid = blockIdx.x;
    const int mb  = (bid & 1) * 128;       // batch base
    const int ub  = (bid >> 1) * 16;       // hidden-unit base

    const int u   = tid & 15;              // unit within tile
    const int m0  = (tid >> 4) * 8;        // first of 8 batch rows

    // loader lane mappings
    const int lm  = tid & 127;             // A tile row
    const int lk4 = (tid >> 7) * 4;        // A tile k offset {0,4}
    const int lc  = tid & 63;              // B tile col (gate*16 + unit)
    const int lkb = (tid >> 6) * 4;        // B tile k offset {0,4,8,12}
    const int wofs = ((lc >> 4) * HID + ub + (lc & 15)) * HID;  // loader's W row offset

    // biases held in registers for the whole run
    float bias0[4], bias1[4];
    #pragma unroll
    for (int gg = 0; gg < 4; ++gg) {
        int r = gg * HID + ub + u;
        bias0[gg] = bih0[r] + bhh0[r];
        bias1[gg] = bih1[r] + bhh1[r];
    }

    // layer-0 input weights (K=6) loaded once
    for (int i = tid; i < 64 * 6; i += NTHR) {
        int c = i / 6, k = i - c * 6;
        Ws6[c][k] = Wih0[((c >> 4) * HID + ub + (c & 15)) * 6 + k];
    }

    // zero h0/h1 initial + cell states (each block zeroes its 2048-float slice)
    {
        int base = bid * (NH / NBLK);
        for (int i = tid; i < NH / NBLK; i += NTHR) {
            g_h0a[base + i] = 0.0f;
            g_h1a[base + i] = 0.0f;
            g_c0[base + i]  = 0.0f;
            g_c1[base + i]  = 0.0f;
        }
    }
    grid_sync();

    #pragma unroll 1
    for (int t = 0; t < L_SEQ; ++t) {
        float* h0p = (t & 1) ? g_h0b : g_h0a;
        float* h0c = (t & 1) ? g_h0a : g_h0b;
        float* h1p = (t & 1) ? g_h1b : g_h1a;
        float* h1c = (t & 1) ? g_h1a : g_h1b;

        // ================= layer 0 =================
        {
            // stage this step's x tile (made visible by gemm's syncthreads)
            const float* xa = seq + (size_t)(t * NB + mb) * 6;
            for (int i = tid; i < 128 * 6; i += NTHR) {
                int r = i / 6, k = i - r * 6;
                Xs[r][k] = xa[r * 6 + k];
            }

            float acc[8][4] = {};
            gemm1024(h0p + mb * HID, Whh0 + wofs, acc, As, Bs, lm, lk4, lc, lkb, m0, u);

            // x projection, K = 6
            #pragma unroll
            for (int k = 0; k < 6; ++k) {
                float b0 = Ws6[u][k], b1 = Ws6[16 + u][k];
                float b2 = Ws6[32 + u][k], b3 = Ws6[48 + u][k];
                #pragma unroll
                for (int i = 0; i < 8; ++i) {
                    float a = Xs[m0 + i][k];
                    acc[i][0] += a * b0; acc[i][1] += a * b1;
                    acc[i][2] += a * b2; acc[i][3] += a * b3;
                }
            }

            #pragma unroll
            for (int i = 0; i < 8; ++i) {
                float iv = sigm(acc[i][0] + bias0[0]);
                float fv = sigm(acc[i][1] + bias0[1]);
                float gv = tanhf(acc[i][2] + bias0[2]);
                float ov = sigm(acc[i][3] + bias0[3]);
                int gi = (mb + m0 + i) * HID + ub + u;
                float c = fv * g_c0[gi] + iv * gv;
                g_c0[gi] = c;
                h0c[gi] = ov * tanhf(c);
            }
        }
        grid_sync();

        // ================= layer 1 =================
        {
            float acc[8][4] = {};
            gemm1024(h0c + mb * HID, Wih1 + wofs, acc, As, Bs, lm, lk4, lc, lkb, m0, u);
            gemm1024(h1p + mb * HID, Whh1 + wofs, acc, As, Bs, lm, lk4, lc, lkb, m0, u);

            #pragma unroll
            for (int i = 0; i < 8; ++i) {
                float iv = sigm(acc[i][0] + bias1[0]);
                float fv = sigm(acc[i][1] + bias1[1]);
                float gv = tanhf(acc[i][2] + bias1[2]);
                float ov = sigm(acc[i][3] + bias1[3]);
                int gi = (mb + m0 + i) * HID + ub + u;
                float c = fv * g_c1[gi] + iv * gv;
                g_c1[gi] = c;
                h1c[gi] = ov * tanhf(c);
            }
        }
        grid_sync();
    }

    // ---- final linear on last layer-1 output (t=511 odd -> wrote g_h1a) ----
    const float* hl = g_h1a;
    #pragma unroll 1
    for (int r = 0; r < 2; ++r) {
        int row = bid * 2 + r;
        const float* hr = hl + (size_t)row * HID;
        float s = 0.0f;
        for (int k = tid; k < HID; k += NTHR) s += hr[k] * linW[k];
        #pragma unroll
        for (int o = 16; o; o >>= 1) s += __shfl_down_sync(0xffffffffu, s, o);
        if ((tid & 31) == 0) red[tid >> 5] = s;
        __syncthreads();
        if (tid == 0) {
            float tot = red[0] + red[1] + red[2] + red[3]
                      + red[4] + red[5] + red[6] + red[7];
            out[row] = tot + linb[0];
        }
        __syncthreads();
    }
}

// ---------------------------------------------------------------------------
// kernel_launch: exactly ONE kernel node -> minimal graph, no residual driver
// upload buffer after teardown.
// ---------------------------------------------------------------------------
extern "C" void kernel_launch(void* const* d_in, const int* in_sizes, int n_in,
                              void* d_out, int out_size)
{
    (void)in_sizes; (void)n_in; (void)out_size;
    lstm_persist<<<NBLK, NTHR>>>(
        (const float*)d_in[0],                      // sequence
        (const float*)d_in[1], (const float*)d_in[2],   // W_ih_0, W_hh_0
        (const float*)d_in[3], (const float*)d_in[4],   // b_ih_0, b_hh_0
        (const float*)d_in[5], (const float*)d_in[6],   // W_ih_1, W_hh_1
        (const float*)d_in[7], (const float*)d_in[8],   // b_ih_1, b_hh_1
        (const float*)d_in[9], (const float*)d_in[10],  // lin_W, lin_b
        (float*)d_out);
}